// round 15
// baseline (speedup 1.0000x reference)
#include <cuda_runtime.h>
#include <cuda_bf16.h>
#include <cuda_fp16.h>
#include <math.h>
#include <stdint.h>

#define BATCH   2
#define SEQ     2048
#define DMODEL  1024
#define NH      16
#define DH      64
#define MROWS   (BATCH*SEQ)   // 4096

// ---------------- scratch (device globals; no allocation allowed) ----------------
__device__ __half g_x16 [MROWS*DMODEL];
__device__ __half g_w316[3*DMODEL*DMODEL];   // Wq,Wk,Wv
__device__ __half g_wo16[DMODEL*DMODEL];
__device__ __half g_ao16[MROWS*DMODEL];

__device__ __half g_q16 [BATCH*NH*SEQ*DH];   // [b,h,s,d]
__device__ __half g_k16 [BATCH*NH*SEQ*DH];   // [b,h,s,d]
__device__ __half g_vt16[BATCH*NH*DH*SEQ];   // [b,h,d,s]
__device__ __half g_er16[SEQ*DH];

// ---------------- helpers ----------------
__device__ __forceinline__ uint32_t smem_u32(const void* p) {
    uint32_t a;
    asm("{ .reg .u64 t; cvta.to.shared.u64 t, %1; cvt.u32.u64 %0, t; }" : "=r"(a) : "l"(p));
    return a;
}

__device__ __forceinline__ void mma_f16(float* c, const uint32_t* a, const uint32_t* b) {
    asm volatile(
        "mma.sync.aligned.m16n8k16.row.col.f32.f16.f16.f32 "
        "{%0,%1,%2,%3}, {%4,%5,%6,%7}, {%8,%9}, {%0,%1,%2,%3};"
        : "+f"(c[0]), "+f"(c[1]), "+f"(c[2]), "+f"(c[3])
        : "r"(a[0]), "r"(a[1]), "r"(a[2]), "r"(a[3]), "r"(b[0]), "r"(b[1]));
}

#define LDSM_X4(r0,r1,r2,r3,addr) \
    asm volatile("ldmatrix.sync.aligned.m8n8.x4.shared.b16 {%0,%1,%2,%3}, [%4];" \
        : "=r"(r0), "=r"(r1), "=r"(r2), "=r"(r3) : "r"(addr))

#define CP16(dst, src) \
    asm volatile("cp.async.cg.shared.global [%0], [%1], 16;" :: "r"(dst), "l"(src))
#define CP16Z(dst, src, sz) \
    asm volatile("cp.async.cg.shared.global [%0], [%1], 16, %2;" :: "r"(dst), "l"(src), "r"(sz))
#define CP_COMMIT() asm volatile("cp.async.commit_group;" ::: "memory")
#define CP_WAITG(n) asm volatile("cp.async.wait_group %0;" :: "n"(n) : "memory")

__device__ __forceinline__ uint32_t pack_h2(float f0, float f1) {
    __half2 p = __floats2half2_rn(f0, f1);
    return *(uint32_t*)&p;
}
__device__ __forceinline__ uint32_t ex2_h2(uint32_t h2) {
    uint32_t r;
    asm("ex2.approx.f16x2 %0, %1;" : "=r"(r) : "r"(h2));
    return r;
}

// ---------------- conversions ----------------
__global__ void __launch_bounds__(256)
cvt_h16(const float* __restrict__ src, __half* __restrict__ dst, int n4)
{
    int i = blockIdx.x * blockDim.x + threadIdx.x;
    if (i >= n4) return;
    float4 v = ((const float4*)src)[i];
    ((__half2*)dst)[2*i+0] = __floats2half2_rn(v.x, v.y);
    ((__half2*)dst)[2*i+1] = __floats2half2_rn(v.z, v.w);
}

__global__ void __launch_bounds__(256)
cvt_w4(const float* __restrict__ wq, const float* __restrict__ wk,
       const float* __restrict__ wv, const float* __restrict__ wo)
{
    const int n4 = DMODEL * DMODEL / 4;
    int i = blockIdx.x * blockDim.x + threadIdx.x;
    if (i >= n4) return;
    const float* src;
    __half* dst;
    switch (blockIdx.y) {
        case 0: src = wq; dst = g_w316;                break;
        case 1: src = wk; dst = g_w316 + (size_t)DMODEL*DMODEL;   break;
        case 2: src = wv; dst = g_w316 + 2*(size_t)DMODEL*DMODEL; break;
        default: src = wo; dst = g_wo16;               break;
    }
    float4 v = ((const float4*)src)[i];
    ((__half2*)dst)[2*i+0] = __floats2half2_rn(v.x, v.y);
    ((__half2*)dst)[2*i+1] = __floats2half2_rn(v.z, v.w);
}

// ================= fp16 GEMM core: BKG=64, 3-stage cp.async ring =================
#define BKG 64
#define LDT 72                              // halfs per row (64 + 8 pad)
#define QKV_BUF 36864                       // 2 tiles x 128 x 144B
#define QKV_SMEM_BYTES (3 * QKV_BUF)        // 110592

__device__ __forceinline__ void gemm16_issue(
    uint32_t sbase,
    const __half* __restrict__ A, const __half* __restrict__ B,
    int m0, int n0, int k0, int lr, int lcB)
{
    const char* pA = (const char*)(A + (size_t)(m0 + lr) * DMODEL + k0) + lcB;
    const char* pB = (const char*)(B + (size_t)(n0 + lr) * DMODEL + k0) + lcB;
    uint32_t d = sbase + lr * (LDT * 2) + lcB;
    #pragma unroll
    for (int c = 0; c < 4; c++) {
        CP16(d + c * 16,                 pA + c * 16);
        CP16(d + c * 16 + 128 * LDT * 2, pB + c * 16);
    }
}

// acc[4][4][4] = A(128xK) . B(128xK)^T tile
__device__ __forceinline__ void gemm16_core(
    const __half* __restrict__ A, const __half* __restrict__ B,
    char* smem, int m0, int n0, float acc[4][4][4])
{
    const int tid  = threadIdx.x;
    const int w    = tid >> 5;
    const int lane = tid & 31;
    const int wm   = (w >> 2) * 64;
    const int wn   = (w & 3) * 32;
    const int l8   = lane & 7;
    const int seg  = lane >> 3;
    const int lr   = tid >> 1;
    const int lcB  = (tid & 1) * 64;        // byte offset of the 4-chunk group

    const uint32_t sb = smem_u32(smem);
    const int NIT = DMODEL / BKG;           // 16

    const uint32_t aA = sb + (uint32_t)(((wm + l8 + (seg & 1) * 8) * LDT + (seg >> 1) * 8) * 2);
    const uint32_t aB = sb + (uint32_t)(128 * LDT * 2 +
                         ((wn + (seg >> 1) * 8 + l8) * LDT + (seg & 1) * 8) * 2);

    #pragma unroll
    for (int mi = 0; mi < 4; mi++)
        #pragma unroll
        for (int ni = 0; ni < 4; ni++)
            #pragma unroll
            for (int e = 0; e < 4; e++) acc[mi][ni][e] = 0.f;

    #pragma unroll
    for (int p = 0; p < 2; p++) {
        gemm16_issue(sb + p * QKV_BUF, A, B, m0, n0, p * BKG, lr, lcB);
        CP_COMMIT();
    }

    for (int it = 0; it < NIT; it++) {
        CP_WAITG(1);
        __syncthreads();
        {
            int nx = it + 2;
            if (nx < NIT)
                gemm16_issue(sb + (nx % 3) * QKV_BUF, A, B, m0, n0, nx * BKG, lr, lcB);
            CP_COMMIT();
        }

        const uint32_t stg = (uint32_t)((it % 3) * QKV_BUF);

        #pragma unroll
        for (int s = 0; s < 4; s++) {
            const uint32_t co = stg + (uint32_t)(s * 32);   // +16 halfs per k-step
            uint32_t a4[4][4], b4[2][4];
            #pragma unroll
            for (int mi = 0; mi < 4; mi++)
                LDSM_X4(a4[mi][0], a4[mi][1], a4[mi][2], a4[mi][3],
                        aA + co + (uint32_t)(mi * 16 * LDT * 2));
            #pragma unroll
            for (int nb = 0; nb < 2; nb++)
                LDSM_X4(b4[nb][0], b4[nb][1], b4[nb][2], b4[nb][3],
                        aB + co + (uint32_t)(nb * 16 * LDT * 2));
            #pragma unroll
            for (int mi = 0; mi < 4; mi++)
                #pragma unroll
                for (int ni = 0; ni < 4; ni++)
                    mma_f16(acc[mi][ni], a4[mi], &b4[ni >> 1][(ni & 1) * 2]);
        }
    }
}

__global__ void __launch_bounds__(256, 2)
mma_qkv(const float* __restrict__ bq, const float* __restrict__ bk, const float* __restrict__ bv)
{
    extern __shared__ char smem[];
    const int z = blockIdx.z;
    const __half* Bw = g_w316 + (size_t)z * DMODEL * DMODEL;
    const float* bias = (z == 0) ? bq : (z == 1) ? bk : bv;

    const int m0 = blockIdx.y * 128;
    const int n0 = blockIdx.x * 128;

    float acc[4][4][4];
    gemm16_core(g_x16, Bw, smem, m0, n0, acc);

    const int lane = threadIdx.x & 31;
    const int w    = threadIdx.x >> 5;
    const int wm   = (w >> 2) * 64;
    const int wn   = (w & 3) * 32;
    const int g    = lane >> 2;
    const int tig  = lane & 3;

    if (z < 2) {
        __half* out16 = (z == 0) ? g_q16 : g_k16;
        #pragma unroll
        for (int mi = 0; mi < 4; mi++) {
            #pragma unroll
            for (int half = 0; half < 2; half++) {
                int m = m0 + wm + mi * 16 + g + half * 8;
                int b = m >> 11;
                int sidx = m & (SEQ - 1);
                #pragma unroll
                for (int ni = 0; ni < 4; ni++) {
                    int n = n0 + wn + ni * 8 + tig * 2;
                    int h  = n >> 6;
                    int dh = n & 63;
                    float v0 = acc[mi][ni][half * 2 + 0] + bias[n];
                    float v1 = acc[mi][ni][half * 2 + 1] + bias[n + 1];
                    size_t idx = (((size_t)(b * NH + h) * SEQ) + sidx) * DH + dh;
                    *(__half2*)&out16[idx] = __floats2half2_rn(v0, v1);
                }
            }
        }
    } else {
        // V: transpose through smem, then coalesced 16B stores to [b,h,d,s]
        __syncthreads();
        __half* st = (__half*)smem;         // [n_local][m_local], pitch 136
        #pragma unroll
        for (int mi = 0; mi < 4; mi++) {
            #pragma unroll
            for (int half = 0; half < 2; half++) {
                int ml = wm + mi * 16 + g + half * 8;
                #pragma unroll
                for (int ni = 0; ni < 4; ni++) {
                    int nl = wn + ni * 8 + tig * 2;
                    int n  = n0 + nl;
                    st[(nl + 0) * 136 + ml] = __float2half(acc[mi][ni][half * 2 + 0] + bias[n]);
                    st[(nl + 1) * 136 + ml] = __float2half(acc[mi][ni][half * 2 + 1] + bias[n + 1]);
                }
            }
        }
        __syncthreads();
        const int b  = m0 >> 11;
        const int s0 = m0 & (SEQ - 1);
        const int r  = (int)threadIdx.x >> 1;
        const int c  = ((int)threadIdx.x & 1) * 64;
        const int h  = (n0 >> 6) + (r >> 6);
        const int dh = r & 63;
        __half* dst = g_vt16 + ((size_t)(b * NH + h) * DH + dh) * SEQ + s0 + c;
        #pragma unroll
        for (int u = 0; u < 64; u += 8)
            *(uint4*)(dst + u) = *(const uint4*)&st[r * 136 + c + u];
    }
}

__global__ void __launch_bounds__(256, 2)
mma_out(const float* __restrict__ bias, float* __restrict__ out)
{
    extern __shared__ char smem[];
    const int m0 = blockIdx.y * 128;
    const int n0 = blockIdx.x * 128;

    float acc[4][4][4];
    gemm16_core(g_ao16, g_wo16, smem, m0, n0, acc);

    const int lane = threadIdx.x & 31;
    const int w    = threadIdx.x >> 5;
    const int wm   = (w >> 2) * 64;
    const int wn   = (w & 3) * 32;
    const int g    = lane >> 2;
    const int tig  = lane & 3;

    #pragma unroll
    for (int mi = 0; mi < 4; mi++) {
        #pragma unroll
        for (int half = 0; half < 2; half++) {
            int m = m0 + wm + mi * 16 + g + half * 8;
            #pragma unroll
            for (int ni = 0; ni < 4; ni++) {
                int n = n0 + wn + ni * 8 + tig * 2;
                float2 v;
                v.x = acc[mi][ni][half * 2 + 0] + bias[n];
                v.y = acc[mi][ni][half * 2 + 1] + bias[n + 1];
                *(float2*)&out[(size_t)m * DMODEL + n] = v;
            }
        }
    }
}

// ---------------- FA2 fp16 attention: 2-stage pipeline, fp16 ce blocks, 2 CTA/SM ----------------
#define P2 72
#define CEH 72                    // half pitch for ce blocks
#define TILE_B  (64*P2*2)         // 9216
#define CE_B    (128*CEH*2)       // 18432 (fp16)
#define ABUF2   (3*CE_B)          // 55296
#define STAGE_B (3*TILE_B)        // 27648 : K, V, E
#define ATTN_SMEM_BYTES (ABUF2 + 2*STAGE_B)  // 110592 -> 2 CTA/SM

#define SCL2 0.18033688011112042f   // 0.125 * log2(e)

__device__ __forceinline__ void qb_gemm16(
    const uint32_t qh[4][4],
    const __half* Bh, float s[8][4], int l8, int seg)
{
    #pragma unroll
    for (int ni = 0; ni < 8; ni++)
        #pragma unroll
        for (int e = 0; e < 4; e++) s[ni][e] = 0.f;
    #pragma unroll
    for (int ks = 0; ks < 4; ks++) {
        int kk = ks * 16;
        #pragma unroll
        for (int nb = 0; nb < 4; nb++) {
            int rowb = nb * 16 + (seg >> 1) * 8 + l8;
            int colb = kk + (seg & 1) * 8;
            uint32_t bh4[4];
            LDSM_X4(bh4[0], bh4[1], bh4[2], bh4[3], smem_u32(&Bh[rowb*P2 + colb]));
            mma_f16(s[2*nb+0], qh[ks], bh4 + 0);
            mma_f16(s[2*nb+1], qh[ks], bh4 + 2);
        }
    }
}

__device__ __forceinline__ void attn_issue16(
    uint32_t sbase, int st,
    const __half* Kg, const __half* Vg,
    int j0, int i0, int lr, int lcc)
{
    uint32_t base = sbase + ABUF2 + st * STAGE_B;
    uint32_t ro   = (uint32_t)(lr * (P2 * 2) + lcc * 2);

    const char* kp = (const char*)(Kg + (size_t)(j0 + lr) * DH + lcc);
    CP16(base + 0 * TILE_B + ro,      kp);
    CP16(base + 0 * TILE_B + ro + 16, kp + 16);

    const char* vp = (const char*)(Vg + (size_t)lr * SEQ + j0 + lcc);
    CP16(base + 1 * TILE_B + ro,      vp);
    CP16(base + 1 * TILE_B + ro + 16, vp + 16);

    int ge = SEQ + j0 - i0 + lr;
    uint32_t sz = (ge < SEQ) ? 16u : 0u;
    int gec = (ge < SEQ) ? ge : 0;
    const char* ep = (const char*)(g_er16 + (size_t)gec * DH + lcc);
    CP16Z(base + 2 * TILE_B + ro,      ep,      sz);
    CP16Z(base + 2 * TILE_B + ro + 16, ep + 16, sz);
}

__global__ void __launch_bounds__(256, 2)
attn_mma()
{
    extern __shared__ char smem[];
    __half* ceBlk0 = (__half*)(smem + 0 * CE_B);
    __half* ceBlk1 = (__half*)(smem + 1 * CE_B);
    __half* ceBlk2 = (__half*)(smem + 2 * CE_B);

    const int tid  = threadIdx.x;
    const int lane = tid & 31;
    const int w    = tid >> 5;
    const int l8   = lane & 7;
    const int seg  = lane >> 3;
    const int wm   = w * 16;

    const int qt = (int)gridDim.x - 1 - (int)blockIdx.x;   // heavy tiles first
    const int bh = blockIdx.y;
    const int i0 = qt * 128;

    const __half* Qg = g_q16  + (size_t)bh * SEQ * DH;
    const __half* Kg = g_k16  + (size_t)bh * SEQ * DH;
    const __half* Vg = g_vt16 + (size_t)bh * DH * SEQ;

    const uint32_t sb = smem_u32(smem);
    const int lr  = tid >> 2;
    const int lcc = (tid & 3) * 16;

    // ---- Q staging (overlaps ce area) ----
    __half* QS = (__half*)(smem);
    {
        int r = tid >> 1;
        int c = (tid & 1) * 32;
        const uint4* sh = (const uint4*)(Qg + (size_t)(i0 + r) * DH + c);
        #pragma unroll
        for (int u = 0; u < 4; u++)
            *(uint4*)&QS[r*P2 + c + u*8] = sh[u];
    }
    // G0: stage0 tiles (j0=0) + initial E blocks -> stage1 K/V slots (in-range rows)
    attn_issue16(sb, 0, Kg, Vg, 0, i0, lr, lcc);
    {
        uint32_t base = sb + ABUF2 + 1 * STAGE_B;
        uint32_t ro   = (uint32_t)(lr * (P2 * 2) + lcc * 2);
        int ge0 = SEQ - i0 - 128 + lr;
        int ge1 = SEQ - i0 - 64 + lr;
        const char* e0 = (const char*)(g_er16 + (size_t)ge0 * DH + lcc);
        const char* e1 = (const char*)(g_er16 + (size_t)ge1 * DH + lcc);
        CP16(base + 0 * TILE_B + ro,      e0);
        CP16(base + 0 * TILE_B + ro + 16, e0 + 16);
        CP16(base + 1 * TILE_B + ro,      e1);
        CP16(base + 1 * TILE_B + ro + 16, e1 + 16);
    }
    CP_COMMIT();
    CP_WAITG(0);
    __syncthreads();          // QS + G0 visible

    // ---- Q A-frags to registers ----
    uint32_t qh[4][4];
    #pragma unroll
    for (int ks = 0; ks < 4; ks++) {
        int row = wm + l8 + (seg & 1) * 8;
        int col = ks * 16 + (seg >> 1) * 8;
        LDSM_X4(qh[ks][0], qh[ks][1], qh[ks][2], qh[ks][3], smem_u32(&QS[row*P2 + col]));
    }
    __syncthreads();          // all warps read Q before ce-init overwrites area

    // ---- init rel blocks ce0, ce1 (fp16, warp-private rows) ----
    {
        const __half* E0 = (const __half*)(smem + ABUF2 + 1*STAGE_B + 0*TILE_B);
        const __half* E1 = (const __half*)(smem + ABUF2 + 1*STAGE_B + 1*TILE_B);
        float r0v[8][4], r1v[8][4];
        qb_gemm16(qh, E0, r0v, l8, seg);
        qb_gemm16(qh, E1, r1v, l8, seg);
        int rr = wm + (lane >> 2);
        #pragma unroll
        for (int ni = 0; ni < 8; ni++) {
            int cc = ni * 8 + (lane & 3) * 2;
            *(uint32_t*)&ceBlk0[rr*CEH + cc]     = pack_h2(r0v[ni][0], r0v[ni][1]);
            *(uint32_t*)&ceBlk0[(rr+8)*CEH + cc] = pack_h2(r0v[ni][2], r0v[ni][3]);
            *(uint32_t*)&ceBlk1[rr*CEH + cc]     = pack_h2(r1v[ni][0], r1v[ni][1]);
            *(uint32_t*)&ceBlk1[(rr+8)*CEH + cc] = pack_h2(r1v[ni][2], r1v[ni][3]);
        }
    }

    const int ra = wm + (lane >> 2);
    const int jb = (lane & 3) * 2;
    const int pa = 127 - ra;
    const int pb = pa - 8;
    const float NEGINF = __int_as_float(0xff800000);

    float l_a = 0.f, l_b = 0.f;
    float O[8][4];
    #pragma unroll
    for (int ni = 0; ni < 8; ni++)
        #pragma unroll
        for (int e = 0; e < 4; e++) O[ni][e] = 0.f;

    __half* c0 = ceBlk0; __half* c1 = ceBlk1; __half* c2 = ceBlk2;

    const int NI = i0 / 64 + 2;
    int t = 0;
    for (int j0 = 0; j0 <= i0 + 64; j0 += 64, t++) {
        CP_WAITG(0);           // group t complete
        __syncthreads();       // all warps done with previous stage / Einit
        if (t + 1 < NI) {
            attn_issue16(sb, (t + 1) & 1, Kg, Vg, j0 + 64, i0, lr, lcc);
            CP_COMMIT();
        }

        const char* stg = smem + ABUF2 + (t & 1) * STAGE_B;
        const __half* KH = (const __half*)(stg + 0*TILE_B);
        const __half* VH = (const __half*)(stg + 1*TILE_B);
        const __half* EH = (const __half*)(stg + 2*TILE_B);

        // ---- new rel block -> c2 (warp-private) ----
        {
            float rv[8][4];
            qb_gemm16(qh, EH, rv, l8, seg);
            #pragma unroll
            for (int ni = 0; ni < 8; ni++) {
                int cc = ni * 8 + jb;
                *(uint32_t*)&c2[ra*CEH + cc]     = pack_h2(rv[ni][0], rv[ni][1]);
                *(uint32_t*)&c2[(ra+8)*CEH + cc] = pack_h2(rv[ni][2], rv[ni][3]);
            }
        }

        // ---- scores in regs ----
        float s[8][4];
        qb_gemm16(qh, KH, s, l8, seg);

        // ---- softmax: (s + rel)*log2e/8, mask -> -inf, ex2.f16x2 ----
        uint32_t Pa[8], Pb[8];
        #pragma unroll
        for (int ni = 0; ni < 8; ni++) {
            float xv[4];
            #pragma unroll
            for (int c = 0; c < 2; c++) {
                int j = ni * 8 + jb + c;
                int offa = j + pa;
                const __half* bpa = (offa < 64) ? c0 : ((offa < 128) ? c1 : c2);
                float va = (s[ni][c] + __half2float(bpa[ra*CEH + (offa & 63)])) * SCL2;
                xv[c] = (j0 + j > i0 + ra) ? NEGINF : va;

                int offb = j + pb;
                const __half* bpb = (offb < 64) ? c0 : ((offb < 128) ? c1 : c2);
                float vb = (s[ni][2+c] + __half2float(bpb[(ra+8)*CEH + (offb & 63)])) * SCL2;
                xv[2+c] = (j0 + j > i0 + ra + 8) ? NEGINF : vb;
            }
            Pa[ni] = ex2_h2(pack_h2(xv[0], xv[1]));
            Pb[ni] = ex2_h2(pack_h2(xv[2], xv[3]));
            float2 fa = __half22float2(*(__half2*)&Pa[ni]);
            float2 fb = __half22float2(*(__half2*)&Pb[ni]);
            l_a += fa.x + fa.y;
            l_b += fb.x + fb.y;
        }

        // ---- PV GEMM: P A-frags directly from Pa/Pb ----
        #pragma unroll
        for (int ks = 0; ks < 4; ks++) {
            uint32_t pah[4] = { Pa[2*ks], Pb[2*ks], Pa[2*ks+1], Pb[2*ks+1] };
            int kk = ks * 16;
            #pragma unroll
            for (int nb = 0; nb < 4; nb++) {
                int rowb = nb * 16 + (seg >> 1) * 8 + l8;
                int colb = kk + (seg & 1) * 8;
                uint32_t vh4[4];
                LDSM_X4(vh4[0], vh4[1], vh4[2], vh4[3], smem_u32(&VH[rowb*P2 + colb]));
                mma_f16(O[2*nb+0], pah, vh4 + 0);
                mma_f16(O[2*nb+1], pah, vh4 + 2);
            }
        }

        __half* tt = c0; c0 = c1; c1 = c2; c2 = tt;
    }

    // ---- epilogue: quad-reduce l, O / l -> g_ao16 ----
    {
        l_a += __shfl_xor_sync(0xffffffffu, l_a, 1);
        l_a += __shfl_xor_sync(0xffffffffu, l_a, 2);
        l_b += __shfl_xor_sync(0xffffffffu, l_b, 1);
        l_b += __shfl_xor_sync(0xffffffffu, l_b, 2);

        int b = bh >> 4;
        int h = bh & 15;
        float inv_a = 1.0f / l_a;
        float inv_b = 1.0f / l_b;
        #pragma unroll
        for (int ni = 0; ni < 8; ni++) {
            int cc = ni * 8 + jb;
            size_t iag = ((size_t)(b*SEQ + i0 + ra))     * DMODEL + h*DH + cc;
            size_t ibg = ((size_t)(b*SEQ + i0 + ra + 8)) * DMODEL + h*DH + cc;
            *(__half2*)&g_ao16[iag] = __floats2half2_rn(O[ni][0] * inv_a, O[ni][1] * inv_a);
            *(__half2*)&g_ao16[ibg] = __floats2half2_rn(O[ni][2] * inv_b, O[ni][3] * inv_b);
        }
    }
}

// ---------------- launch ----------------
extern "C" void kernel_launch(void* const* d_in, const int* in_sizes, int n_in,
                              void* d_out, int out_size)
{
    const float* x  = (const float*)d_in[0];
    // d_in[1] = mask (unused: causal structure applied directly; identical numerics)
    const float* Wq = (const float*)d_in[2];
    const float* bq = (const float*)d_in[3];
    const float* Wk = (const float*)d_in[4];
    const float* bk = (const float*)d_in[5];
    const float* Wv = (const float*)d_in[6];
    const float* bv = (const float*)d_in[7];
    const float* Er = (const float*)d_in[8];
    const float* Wo = (const float*)d_in[9];
    const float* bo = (const float*)d_in[10];
    float* out = (float*)d_out;

    (void)in_sizes; (void)n_in; (void)out_size;

    __half *x16, *er16;
    cudaGetSymbolAddress((void**)&x16,  g_x16);
    cudaGetSymbolAddress((void**)&er16, g_er16);

    cudaFuncSetAttribute(mma_qkv, cudaFuncAttributeMaxDynamicSharedMemorySize,
                         QKV_SMEM_BYTES);
    cudaFuncSetAttribute(mma_out, cudaFuncAttributeMaxDynamicSharedMemorySize,
                         QKV_SMEM_BYTES);
    cudaFuncSetAttribute(attn_mma, cudaFuncAttributeMaxDynamicSharedMemorySize,
                         ATTN_SMEM_BYTES);

    {
        int n4 = MROWS * DMODEL / 4;
        cvt_h16<<<(n4 + 255) / 256, 256>>>(x, x16, n4);
    }
    {
        int n4 = DMODEL * DMODEL / 4;
        cvt_w4<<<dim3((n4 + 255) / 256, 4), 256>>>(Wq, Wk, Wv, Wo);
    }
    {
        int n4 = SEQ * DH / 4;
        cvt_h16<<<(n4 + 255) / 256, 256>>>(Er, er16, n4);
    }

    // QKV projections (fp16 HMMA, BKG=64, 3-stage cp.async)
    mma_qkv<<<dim3(DMODEL/128, MROWS/128, 3), 256, QKV_SMEM_BYTES>>>(bq, bk, bv);

    // attention (fp16 HMMA, 2-stage cp.async, fp16 ce, 2 CTA/SM)
    attn_mma<<<dim3(SEQ/128, BATCH*NH), 256, ATTN_SMEM_BYTES>>>();

    // output projection (fp16 HMMA, BKG=64)
    mma_out<<<dim3(DMODEL/128, MROWS/128), 256, QKV_SMEM_BYTES>>>(bo, out);
}

// round 16
// speedup vs baseline: 1.1196x; 1.1196x over previous
#include <cuda_runtime.h>
#include <cuda_bf16.h>
#include <cuda_fp16.h>
#include <math.h>
#include <stdint.h>

#define BATCH   2
#define SEQ     2048
#define DMODEL  1024
#define NH      16
#define DH      64
#define MROWS   (BATCH*SEQ)   // 4096

// ---------------- scratch (device globals; no allocation allowed) ----------------
__device__ __half g_x16 [MROWS*DMODEL];
__device__ __half g_w316[3*DMODEL*DMODEL];   // Wq,Wk,Wv
__device__ __half g_wo16[DMODEL*DMODEL];
__device__ __half g_ao16[MROWS*DMODEL];

__device__ __half g_q16 [BATCH*NH*SEQ*DH];   // [b,h,s,d]
__device__ __half g_k16 [BATCH*NH*SEQ*DH];   // [b,h,s,d]
__device__ __half g_vt16[BATCH*NH*DH*SEQ];   // [b,h,d,s]
__device__ __half g_er16[SEQ*DH];

// ---------------- helpers ----------------
__device__ __forceinline__ uint32_t smem_u32(const void* p) {
    uint32_t a;
    asm("{ .reg .u64 t; cvta.to.shared.u64 t, %1; cvt.u32.u64 %0, t; }" : "=r"(a) : "l"(p));
    return a;
}

__device__ __forceinline__ void mma_f16(float* c, const uint32_t* a, const uint32_t* b) {
    asm volatile(
        "mma.sync.aligned.m16n8k16.row.col.f32.f16.f16.f32 "
        "{%0,%1,%2,%3}, {%4,%5,%6,%7}, {%8,%9}, {%0,%1,%2,%3};"
        : "+f"(c[0]), "+f"(c[1]), "+f"(c[2]), "+f"(c[3])
        : "r"(a[0]), "r"(a[1]), "r"(a[2]), "r"(a[3]), "r"(b[0]), "r"(b[1]));
}

#define LDSM_X4(r0,r1,r2,r3,addr) \
    asm volatile("ldmatrix.sync.aligned.m8n8.x4.shared.b16 {%0,%1,%2,%3}, [%4];" \
        : "=r"(r0), "=r"(r1), "=r"(r2), "=r"(r3) : "r"(addr))

#define CP16(dst, src) \
    asm volatile("cp.async.cg.shared.global [%0], [%1], 16;" :: "r"(dst), "l"(src))
#define CP16Z(dst, src, sz) \
    asm volatile("cp.async.cg.shared.global [%0], [%1], 16, %2;" :: "r"(dst), "l"(src), "r"(sz))
#define CP_COMMIT() asm volatile("cp.async.commit_group;" ::: "memory")
#define CP_WAITG(n) asm volatile("cp.async.wait_group %0;" :: "n"(n) : "memory")

__device__ __forceinline__ uint32_t pack_h2(float f0, float f1) {
    __half2 p = __floats2half2_rn(f0, f1);
    return *(uint32_t*)&p;
}
__device__ __forceinline__ uint32_t ex2_h2(uint32_t h2) {
    uint32_t r;
    asm("ex2.approx.f16x2 %0, %1;" : "=r"(r) : "r"(h2));
    return r;
}

// ---------------- conversions ----------------
__global__ void __launch_bounds__(256)
cvt_h16(const float* __restrict__ src, __half* __restrict__ dst, int n4)
{
    int i = blockIdx.x * blockDim.x + threadIdx.x;
    if (i >= n4) return;
    float4 v = ((const float4*)src)[i];
    ((__half2*)dst)[2*i+0] = __floats2half2_rn(v.x, v.y);
    ((__half2*)dst)[2*i+1] = __floats2half2_rn(v.z, v.w);
}

__global__ void __launch_bounds__(256)
cvt_w4(const float* __restrict__ wq, const float* __restrict__ wk,
       const float* __restrict__ wv, const float* __restrict__ wo)
{
    const int n4 = DMODEL * DMODEL / 4;
    int i = blockIdx.x * blockDim.x + threadIdx.x;
    if (i >= n4) return;
    const float* src;
    __half* dst;
    switch (blockIdx.y) {
        case 0: src = wq; dst = g_w316;                break;
        case 1: src = wk; dst = g_w316 + (size_t)DMODEL*DMODEL;   break;
        case 2: src = wv; dst = g_w316 + 2*(size_t)DMODEL*DMODEL; break;
        default: src = wo; dst = g_wo16;               break;
    }
    float4 v = ((const float4*)src)[i];
    ((__half2*)dst)[2*i+0] = __floats2half2_rn(v.x, v.y);
    ((__half2*)dst)[2*i+1] = __floats2half2_rn(v.z, v.w);
}

// ================= fp16 GEMM core: BKG=32, 4-stage cp.async ring (R14 proven) =================
#define BKG 32
#define LDT 40
#define QKV_BUF 20480                      // one stage: 2 tiles x 128 x 80B
#define QKV_SMEM_BYTES (4 * QKV_BUF)       // 81920

__device__ __forceinline__ void gemm16_issue(
    uint32_t sbase,
    const __half* __restrict__ A, const __half* __restrict__ B,
    int m0, int n0, int k0, int lr, int lc)
{
    const char* pA = (const char*)(A + (size_t)(m0 + lr) * DMODEL + k0) + lc * 16;
    const char* pB = (const char*)(B + (size_t)(n0 + lr) * DMODEL + k0) + lc * 16;
    uint32_t d = sbase + lr * (LDT * 2) + lc * 16;
    CP16(d + 0 * 128 * LDT * 2 +  0, pA);
    CP16(d + 0 * 128 * LDT * 2 + 16, pA + 16);
    CP16(d + 1 * 128 * LDT * 2 +  0, pB);
    CP16(d + 1 * 128 * LDT * 2 + 16, pB + 16);
}

// acc[4][4][4] = A(128xK) . B(128xK)^T tile; hoisted addresses + full-frag prefetch
__device__ __forceinline__ void gemm16_core(
    const __half* __restrict__ A, const __half* __restrict__ B,
    char* smem, int m0, int n0, float acc[4][4][4])
{
    const int tid  = threadIdx.x;
    const int w    = tid >> 5;
    const int lane = tid & 31;
    const int wm   = (w >> 2) * 64;
    const int wn   = (w & 3) * 32;
    const int l8   = lane & 7;
    const int seg  = lane >> 3;
    const int lr   = tid >> 1;
    const int lc   = (tid & 1) * 2;

    const uint32_t sb = smem_u32(smem);
    const int NIT = DMODEL / BKG;   // 32

    const uint32_t aA = sb + (uint32_t)(((wm + l8 + (seg & 1) * 8) * LDT + (seg >> 1) * 8) * 2);
    const uint32_t aB = sb + (uint32_t)(128 * LDT * 2 +
                         ((wn + (seg >> 1) * 8 + l8) * LDT + (seg & 1) * 8) * 2);

    #pragma unroll
    for (int mi = 0; mi < 4; mi++)
        #pragma unroll
        for (int ni = 0; ni < 4; ni++)
            #pragma unroll
            for (int e = 0; e < 4; e++) acc[mi][ni][e] = 0.f;

    #pragma unroll
    for (int p = 0; p < 3; p++) {
        gemm16_issue(sb + p * QKV_BUF, A, B, m0, n0, p * BKG, lr, lc);
        CP_COMMIT();
    }

    for (int it = 0; it < NIT; it++) {
        CP_WAITG(2);
        __syncthreads();
        {
            int nx = it + 3;
            if (nx < NIT)
                gemm16_issue(sb + (nx & 3) * QKV_BUF, A, B, m0, n0, nx * BKG, lr, lc);
            CP_COMMIT();
        }

        const uint32_t stg = (uint32_t)((it & 3) * QKV_BUF);

        uint32_t a4[2][4][4], b4[2][2][4];
        #pragma unroll
        for (int s = 0; s < 2; s++) {
            uint32_t co = stg + (uint32_t)(s * 32);
            #pragma unroll
            for (int mi = 0; mi < 4; mi++)
                LDSM_X4(a4[s][mi][0], a4[s][mi][1], a4[s][mi][2], a4[s][mi][3],
                        aA + co + (uint32_t)(mi * 16 * LDT * 2));
            #pragma unroll
            for (int nb = 0; nb < 2; nb++)
                LDSM_X4(b4[s][nb][0], b4[s][nb][1], b4[s][nb][2], b4[s][nb][3],
                        aB + co + (uint32_t)(nb * 16 * LDT * 2));
        }
        #pragma unroll
        for (int s = 0; s < 2; s++)
            #pragma unroll
            for (int mi = 0; mi < 4; mi++)
                #pragma unroll
                for (int ni = 0; ni < 4; ni++)
                    mma_f16(acc[mi][ni], a4[s][mi], &b4[s][ni >> 1][(ni & 1) * 2]);
    }
}

__global__ void __launch_bounds__(256, 2)
mma_qkv(const float* __restrict__ bq, const float* __restrict__ bk, const float* __restrict__ bv)
{
    extern __shared__ char smem[];
    const int z = blockIdx.z;
    const __half* Bw = g_w316 + (size_t)z * DMODEL * DMODEL;
    const float* bias = (z == 0) ? bq : (z == 1) ? bk : bv;

    const int m0 = blockIdx.y * 128;
    const int n0 = blockIdx.x * 128;

    float acc[4][4][4];
    gemm16_core(g_x16, Bw, smem, m0, n0, acc);

    const int lane = threadIdx.x & 31;
    const int w    = threadIdx.x >> 5;
    const int wm   = (w >> 2) * 64;
    const int wn   = (w & 3) * 32;
    const int g    = lane >> 2;
    const int tig  = lane & 3;

    if (z < 2) {
        __half* out16 = (z == 0) ? g_q16 : g_k16;
        #pragma unroll
        for (int mi = 0; mi < 4; mi++) {
            #pragma unroll
            for (int half = 0; half < 2; half++) {
                int m = m0 + wm + mi * 16 + g + half * 8;
                int b = m >> 11;
                int sidx = m & (SEQ - 1);
                #pragma unroll
                for (int ni = 0; ni < 4; ni++) {
                    int n = n0 + wn + ni * 8 + tig * 2;
                    int h  = n >> 6;
                    int dh = n & 63;
                    float v0 = acc[mi][ni][half * 2 + 0] + bias[n];
                    float v1 = acc[mi][ni][half * 2 + 1] + bias[n + 1];
                    size_t idx = (((size_t)(b * NH + h) * SEQ) + sidx) * DH + dh;
                    *(__half2*)&out16[idx] = __floats2half2_rn(v0, v1);
                }
            }
        }
    } else {
        // V: transpose through smem, then coalesced 16B stores to [b,h,d,s]
        __syncthreads();
        __half* st = (__half*)smem;         // [n_local][m_local], pitch 136
        #pragma unroll
        for (int mi = 0; mi < 4; mi++) {
            #pragma unroll
            for (int half = 0; half < 2; half++) {
                int ml = wm + mi * 16 + g + half * 8;
                #pragma unroll
                for (int ni = 0; ni < 4; ni++) {
                    int nl = wn + ni * 8 + tig * 2;
                    int n  = n0 + nl;
                    st[(nl + 0) * 136 + ml] = __float2half(acc[mi][ni][half * 2 + 0] + bias[n]);
                    st[(nl + 1) * 136 + ml] = __float2half(acc[mi][ni][half * 2 + 1] + bias[n + 1]);
                }
            }
        }
        __syncthreads();
        const int b  = m0 >> 11;
        const int s0 = m0 & (SEQ - 1);
        const int r  = (int)threadIdx.x >> 1;
        const int c  = ((int)threadIdx.x & 1) * 64;
        const int h  = (n0 >> 6) + (r >> 6);
        const int dh = r & 63;
        __half* dst = g_vt16 + ((size_t)(b * NH + h) * DH + dh) * SEQ + s0 + c;
        #pragma unroll
        for (int u = 0; u < 64; u += 8)
            *(uint4*)(dst + u) = *(const uint4*)&st[r * 136 + c + u];
    }
}

__global__ void __launch_bounds__(256, 2)
mma_out(const float* __restrict__ bias, float* __restrict__ out)
{
    extern __shared__ char smem[];
    const int m0 = blockIdx.y * 128;
    const int n0 = blockIdx.x * 128;

    float acc[4][4][4];
    gemm16_core(g_ao16, g_wo16, smem, m0, n0, acc);

    const int lane = threadIdx.x & 31;
    const int w    = threadIdx.x >> 5;
    const int wm   = (w >> 2) * 64;
    const int wn   = (w & 3) * 32;
    const int g    = lane >> 2;
    const int tig  = lane & 3;

    #pragma unroll
    for (int mi = 0; mi < 4; mi++) {
        #pragma unroll
        for (int half = 0; half < 2; half++) {
            int m = m0 + wm + mi * 16 + g + half * 8;
            #pragma unroll
            for (int ni = 0; ni < 4; ni++) {
                int n = n0 + wn + ni * 8 + tig * 2;
                float2 v;
                v.x = acc[mi][ni][half * 2 + 0] + bias[n];
                v.y = acc[mi][ni][half * 2 + 1] + bias[n + 1];
                *(float2*)&out[(size_t)m * DMODEL + n] = v;
            }
        }
    }
}

// ---------------- FA2 fp16 attention: 2-stage pipeline, fp16 ce blocks, 2 CTA/SM ----------------
#define P2 72
#define CEH 72                    // half pitch for ce blocks
#define TILE_B  (64*P2*2)         // 9216
#define CE_B    (128*CEH*2)       // 18432 (fp16)
#define ABUF2   (3*CE_B)          // 55296
#define STAGE_B (3*TILE_B)        // 27648 : K, V, E
#define ATTN_SMEM_BYTES (ABUF2 + 2*STAGE_B)  // 110592 -> 2 CTA/SM

#define SCL2 0.18033688011112042f   // 0.125 * log2(e)

__device__ __forceinline__ void qb_gemm16(
    const uint32_t qh[4][4],
    const __half* Bh, float s[8][4], int l8, int seg)
{
    #pragma unroll
    for (int ni = 0; ni < 8; ni++)
        #pragma unroll
        for (int e = 0; e < 4; e++) s[ni][e] = 0.f;
    #pragma unroll
    for (int ks = 0; ks < 4; ks++) {
        int kk = ks * 16;
        #pragma unroll
        for (int nb = 0; nb < 4; nb++) {
            int rowb = nb * 16 + (seg >> 1) * 8 + l8;
            int colb = kk + (seg & 1) * 8;
            uint32_t bh4[4];
            LDSM_X4(bh4[0], bh4[1], bh4[2], bh4[3], smem_u32(&Bh[rowb*P2 + colb]));
            mma_f16(s[2*nb+0], qh[ks], bh4 + 0);
            mma_f16(s[2*nb+1], qh[ks], bh4 + 2);
        }
    }
}

__device__ __forceinline__ void attn_issue16(
    uint32_t sbase, int st,
    const __half* Kg, const __half* Vg,
    int j0, int i0, int lr, int lcc)
{
    uint32_t base = sbase + ABUF2 + st * STAGE_B;
    uint32_t ro   = (uint32_t)(lr * (P2 * 2) + lcc * 2);

    const char* kp = (const char*)(Kg + (size_t)(j0 + lr) * DH + lcc);
    CP16(base + 0 * TILE_B + ro,      kp);
    CP16(base + 0 * TILE_B + ro + 16, kp + 16);

    const char* vp = (const char*)(Vg + (size_t)lr * SEQ + j0 + lcc);
    CP16(base + 1 * TILE_B + ro,      vp);
    CP16(base + 1 * TILE_B + ro + 16, vp + 16);

    int ge = SEQ + j0 - i0 + lr;
    uint32_t sz = (ge < SEQ) ? 16u : 0u;
    int gec = (ge < SEQ) ? ge : 0;
    const char* ep = (const char*)(g_er16 + (size_t)gec * DH + lcc);
    CP16Z(base + 2 * TILE_B + ro,      ep,      sz);
    CP16Z(base + 2 * TILE_B + ro + 16, ep + 16, sz);
}

__global__ void __launch_bounds__(256, 2)
attn_mma()
{
    extern __shared__ char smem[];
    __half* ceBlk0 = (__half*)(smem + 0 * CE_B);
    __half* ceBlk1 = (__half*)(smem + 1 * CE_B);
    __half* ceBlk2 = (__half*)(smem + 2 * CE_B);

    const int tid  = threadIdx.x;
    const int lane = tid & 31;
    const int w    = tid >> 5;
    const int l8   = lane & 7;
    const int seg  = lane >> 3;
    const int wm   = w * 16;

    const int qt = (int)gridDim.x - 1 - (int)blockIdx.x;   // heavy tiles first
    const int bh = blockIdx.y;
    const int i0 = qt * 128;

    const __half* Qg = g_q16  + (size_t)bh * SEQ * DH;
    const __half* Kg = g_k16  + (size_t)bh * SEQ * DH;
    const __half* Vg = g_vt16 + (size_t)bh * DH * SEQ;

    const uint32_t sb = smem_u32(smem);
    const int lr  = tid >> 2;
    const int lcc = (tid & 3) * 16;

    // ---- Q staging (overlaps ce area) ----
    __half* QS = (__half*)(smem);
    {
        int r = tid >> 1;
        int c = (tid & 1) * 32;
        const uint4* sh = (const uint4*)(Qg + (size_t)(i0 + r) * DH + c);
        #pragma unroll
        for (int u = 0; u < 4; u++)
            *(uint4*)&QS[r*P2 + c + u*8] = sh[u];
    }
    attn_issue16(sb, 0, Kg, Vg, 0, i0, lr, lcc);
    {
        uint32_t base = sb + ABUF2 + 1 * STAGE_B;
        uint32_t ro   = (uint32_t)(lr * (P2 * 2) + lcc * 2);
        int ge0 = SEQ - i0 - 128 + lr;
        int ge1 = SEQ - i0 - 64 + lr;
        const char* e0 = (const char*)(g_er16 + (size_t)ge0 * DH + lcc);
        const char* e1 = (const char*)(g_er16 + (size_t)ge1 * DH + lcc);
        CP16(base + 0 * TILE_B + ro,      e0);
        CP16(base + 0 * TILE_B + ro + 16, e0 + 16);
        CP16(base + 1 * TILE_B + ro,      e1);
        CP16(base + 1 * TILE_B + ro + 16, e1 + 16);
    }
    CP_COMMIT();
    CP_WAITG(0);
    __syncthreads();          // QS + G0 visible

    // ---- Q A-frags to registers ----
    uint32_t qh[4][4];
    #pragma unroll
    for (int ks = 0; ks < 4; ks++) {
        int row = wm + l8 + (seg & 1) * 8;
        int col = ks * 16 + (seg >> 1) * 8;
        LDSM_X4(qh[ks][0], qh[ks][1], qh[ks][2], qh[ks][3], smem_u32(&QS[row*P2 + col]));
    }
    __syncthreads();          // all warps read Q before ce-init overwrites area

    // ---- init rel blocks ce0, ce1 (fp16, warp-private rows) ----
    {
        const __half* E0 = (const __half*)(smem + ABUF2 + 1*STAGE_B + 0*TILE_B);
        const __half* E1 = (const __half*)(smem + ABUF2 + 1*STAGE_B + 1*TILE_B);
        float r0v[8][4], r1v[8][4];
        qb_gemm16(qh, E0, r0v, l8, seg);
        qb_gemm16(qh, E1, r1v, l8, seg);
        int rr = wm + (lane >> 2);
        #pragma unroll
        for (int ni = 0; ni < 8; ni++) {
            int cc = ni * 8 + (lane & 3) * 2;
            *(uint32_t*)&ceBlk0[rr*CEH + cc]     = pack_h2(r0v[ni][0], r0v[ni][1]);
            *(uint32_t*)&ceBlk0[(rr+8)*CEH + cc] = pack_h2(r0v[ni][2], r0v[ni][3]);
            *(uint32_t*)&ceBlk1[rr*CEH + cc]     = pack_h2(r1v[ni][0], r1v[ni][1]);
            *(uint32_t*)&ceBlk1[(rr+8)*CEH + cc] = pack_h2(r1v[ni][2], r1v[ni][3]);
        }
    }

    const int ra = wm + (lane >> 2);
    const int jb = (lane & 3) * 2;
    const int pa = 127 - ra;
    const int pb = pa - 8;
    const float NEGINF = __int_as_float(0xff800000);

    float l_a = 0.f, l_b = 0.f;
    float O[8][4];
    #pragma unroll
    for (int ni = 0; ni < 8; ni++)
        #pragma unroll
        for (int e = 0; e < 4; e++) O[ni][e] = 0.f;

    __half* c0 = ceBlk0; __half* c1 = ceBlk1; __half* c2 = ceBlk2;

    const int NI = i0 / 64 + 2;
    int t = 0;
    for (int j0 = 0; j0 <= i0 + 64; j0 += 64, t++) {
        CP_WAITG(0);
        __syncthreads();
        if (t + 1 < NI) {
            attn_issue16(sb, (t + 1) & 1, Kg, Vg, j0 + 64, i0, lr, lcc);
            CP_COMMIT();
        }

        const char* stg = smem + ABUF2 + (t & 1) * STAGE_B;
        const __half* KH = (const __half*)(stg + 0*TILE_B);
        const __half* VH = (const __half*)(stg + 1*TILE_B);
        const __half* EH = (const __half*)(stg + 2*TILE_B);

        // ---- new rel block -> c2 (warp-private) ----
        {
            float rv[8][4];
            qb_gemm16(qh, EH, rv, l8, seg);
            #pragma unroll
            for (int ni = 0; ni < 8; ni++) {
                int cc = ni * 8 + jb;
                *(uint32_t*)&c2[ra*CEH + cc]     = pack_h2(rv[ni][0], rv[ni][1]);
                *(uint32_t*)&c2[(ra+8)*CEH + cc] = pack_h2(rv[ni][2], rv[ni][3]);
            }
        }

        // ---- scores in regs ----
        float s[8][4];
        qb_gemm16(qh, KH, s, l8, seg);

        // ---- softmax: (s + rel)*log2e/8, mask -> -inf, ex2.f16x2 ----
        uint32_t Pa[8], Pb[8];
        #pragma unroll
        for (int ni = 0; ni < 8; ni++) {
            float xv[4];
            #pragma unroll
            for (int c = 0; c < 2; c++) {
                int j = ni * 8 + jb + c;
                int offa = j + pa;
                const __half* bpa = (offa < 64) ? c0 : ((offa < 128) ? c1 : c2);
                float va = (s[ni][c] + __half2float(bpa[ra*CEH + (offa & 63)])) * SCL2;
                xv[c] = (j0 + j > i0 + ra) ? NEGINF : va;

                int offb = j + pb;
                const __half* bpb = (offb < 64) ? c0 : ((offb < 128) ? c1 : c2);
                float vb = (s[ni][2+c] + __half2float(bpb[(ra+8)*CEH + (offb & 63)])) * SCL2;
                xv[2+c] = (j0 + j > i0 + ra + 8) ? NEGINF : vb;
            }
            Pa[ni] = ex2_h2(pack_h2(xv[0], xv[1]));
            Pb[ni] = ex2_h2(pack_h2(xv[2], xv[3]));
            float2 fa = __half22float2(*(__half2*)&Pa[ni]);
            float2 fb = __half22float2(*(__half2*)&Pb[ni]);
            l_a += fa.x + fa.y;
            l_b += fb.x + fb.y;
        }

        // ---- PV GEMM: P A-frags directly from Pa/Pb ----
        #pragma unroll
        for (int ks = 0; ks < 4; ks++) {
            uint32_t pah[4] = { Pa[2*ks], Pb[2*ks], Pa[2*ks+1], Pb[2*ks+1] };
            int kk = ks * 16;
            #pragma unroll
            for (int nb = 0; nb < 4; nb++) {
                int rowb = nb * 16 + (seg >> 1) * 8 + l8;
                int colb = kk + (seg & 1) * 8;
                uint32_t vh4[4];
                LDSM_X4(vh4[0], vh4[1], vh4[2], vh4[3], smem_u32(&VH[rowb*P2 + colb]));
                mma_f16(O[2*nb+0], pah, vh4 + 0);
                mma_f16(O[2*nb+1], pah, vh4 + 2);
            }
        }

        __half* tt = c0; c0 = c1; c1 = c2; c2 = tt;
    }

    // ---- epilogue: quad-reduce l, O / l -> g_ao16 ----
    {
        l_a += __shfl_xor_sync(0xffffffffu, l_a, 1);
        l_a += __shfl_xor_sync(0xffffffffu, l_a, 2);
        l_b += __shfl_xor_sync(0xffffffffu, l_b, 1);
        l_b += __shfl_xor_sync(0xffffffffu, l_b, 2);

        int b = bh >> 4;
        int h = bh & 15;
        float inv_a = 1.0f / l_a;
        float inv_b = 1.0f / l_b;
        #pragma unroll
        for (int ni = 0; ni < 8; ni++) {
            int cc = ni * 8 + jb;
            size_t iag = ((size_t)(b*SEQ + i0 + ra))     * DMODEL + h*DH + cc;
            size_t ibg = ((size_t)(b*SEQ + i0 + ra + 8)) * DMODEL + h*DH + cc;
            *(__half2*)&g_ao16[iag] = __floats2half2_rn(O[ni][0] * inv_a, O[ni][1] * inv_a);
            *(__half2*)&g_ao16[ibg] = __floats2half2_rn(O[ni][2] * inv_b, O[ni][3] * inv_b);
        }
    }
}

// ---------------- launch ----------------
extern "C" void kernel_launch(void* const* d_in, const int* in_sizes, int n_in,
                              void* d_out, int out_size)
{
    const float* x  = (const float*)d_in[0];
    // d_in[1] = mask (unused: causal structure applied directly; identical numerics)
    const float* Wq = (const float*)d_in[2];
    const float* bq = (const float*)d_in[3];
    const float* Wk = (const float*)d_in[4];
    const float* bk = (const float*)d_in[5];
    const float* Wv = (const float*)d_in[6];
    const float* bv = (const float*)d_in[7];
    const float* Er = (const float*)d_in[8];
    const float* Wo = (const float*)d_in[9];
    const float* bo = (const float*)d_in[10];
    float* out = (float*)d_out;

    (void)in_sizes; (void)n_in; (void)out_size;

    __half *x16, *er16;
    cudaGetSymbolAddress((void**)&x16,  g_x16);
    cudaGetSymbolAddress((void**)&er16, g_er16);

    cudaFuncSetAttribute(mma_qkv, cudaFuncAttributeMaxDynamicSharedMemorySize,
                         QKV_SMEM_BYTES);
    cudaFuncSetAttribute(mma_out, cudaFuncAttributeMaxDynamicSharedMemorySize,
                         QKV_SMEM_BYTES);
    cudaFuncSetAttribute(attn_mma, cudaFuncAttributeMaxDynamicSharedMemorySize,
                         ATTN_SMEM_BYTES);

    {
        int n4 = MROWS * DMODEL / 4;
        cvt_h16<<<(n4 + 255) / 256, 256>>>(x, x16, n4);
    }
    {
        int n4 = DMODEL * DMODEL / 4;
        cvt_w4<<<dim3((n4 + 255) / 256, 4), 256>>>(Wq, Wk, Wv, Wo);
    }
    {
        int n4 = SEQ * DH / 4;
        cvt_h16<<<(n4 + 255) / 256, 256>>>(Er, er16, n4);
    }

    // QKV projections (fp16 HMMA, BKG=32, 4-stage cp.async — R14 proven core)
    mma_qkv<<<dim3(DMODEL/128, MROWS/128, 3), 256, QKV_SMEM_BYTES>>>(bq, bk, bv);

    // attention (fp16 HMMA, 2-stage cp.async, fp16 ce, 2 CTA/SM)
    attn_mma<<<dim3(SEQ/128, BATCH*NH), 256, ATTN_SMEM_BYTES>>>();

    // output projection (fp16 HMMA, BKG=32)
    mma_out<<<dim3(DMODEL/128, MROWS/128), 256, QKV_SMEM_BYTES>>>(bo, out);
}